// round 6
// baseline (speedup 1.0000x reference)
#include <cuda_runtime.h>
#include <cuda_fp16.h>

// ---------------- problem constants (fixed shapes) ----------------
#define Nn   65536          // total nodes
#define Ee   2097152        // edges
#define EPAD (Ee + 4 * Nn)  // CSR rows padded to multiples of 4
#define HID  32
#define GNUM 8
#define ISZ  8192
#define OSZ  33
#define FEAT (Nn * HID)

// ---------------- static device scratch ----------------
__device__ __align__(128) float g_dinv[Nn];
__device__ __align__(128) int   g_deg[Nn];
__device__ __align__(128) int   g_indeg[Nn];
__device__ int   g_bsum[256];
__device__ int   g_boff[256];
__device__ __align__(128) int   g_rowptr[Nn + 1];
__device__ int   g_cursor[Nn];
__device__ __align__(128) int2  g_epack[EPAD];        // (src, weight bits), padded
__device__ __align__(128) float g_ts[5][Nn];          // scalar Chebyshev terms, layer 1
__device__ __align__(128) float g_buf0[FEAT];
__device__ __align__(128) float g_buf1[FEAT];
__device__ __align__(128) float g_buf2[FEAT];
__device__ __align__(128) float g_accb[FEAT];
__device__ __align__(128) __half g_h16a[FEAT];        // fp16 gather copies (ping-pong)
__device__ __align__(128) __half g_h16b[FEAT];

// ---------------- setup kernels ----------------
__global__ void k_hist(const int* __restrict__ src, const int* __restrict__ dst) {
    int e = blockIdx.x * blockDim.x + threadIdx.x;
    if (e < Ee) {
        atomicAdd(&g_deg[src[e]], 1);
        atomicAdd(&g_indeg[dst[e]], 1);
    }
}

__global__ void k_dinv() {
    int i = blockIdx.x * blockDim.x + threadIdx.x;
    if (i < Nn) {
        int d = g_deg[i];
        g_dinv[i] = (d > 0) ? rsqrtf((float)d) : 0.0f;
    }
}

// ---- 3-stage parallel exclusive scan of padded indeg -> g_rowptr / g_cursor ----
__global__ void k_bsum() {               // 256 blocks x 256 threads
    __shared__ int sh[256];
    int t = threadIdx.x;
    sh[t] = (g_indeg[blockIdx.x * 256 + t] + 3) & ~3;
    __syncthreads();
    for (int off = 128; off > 0; off >>= 1) {
        if (t < off) sh[t] += sh[t + off];
        __syncthreads();
    }
    if (t == 0) g_bsum[blockIdx.x] = sh[0];
}

__global__ void k_bscan() {              // 1 block x 256 threads
    __shared__ int sh[256];
    int t = threadIdx.x;
    sh[t] = g_bsum[t];
    __syncthreads();
    for (int off = 1; off < 256; off <<= 1) {
        int v = (t >= off) ? sh[t - off] : 0;
        __syncthreads();
        sh[t] += v;
        __syncthreads();
    }
    g_boff[t] = (t == 0) ? 0 : sh[t - 1];
}

__global__ void k_rowptr() {             // 256 blocks x 256 threads
    __shared__ int sh[256];
    int t = threadIdx.x;
    int i = blockIdx.x * 256 + t;
    int v = (g_indeg[i] + 3) & ~3;
    sh[t] = v;
    __syncthreads();
    for (int off = 1; off < 256; off <<= 1) {
        int u = (t >= off) ? sh[t - off] : 0;
        __syncthreads();
        sh[t] += u;
        __syncthreads();
    }
    int excl = sh[t] - v + g_boff[blockIdx.x];
    g_rowptr[i] = excl;
    g_cursor[i] = excl;
    if (i == Nn - 1) g_rowptr[Nn] = excl + v;
}

__global__ void k_scatter(const int* __restrict__ src, const int* __restrict__ dst) {
    int e = blockIdx.x * blockDim.x + threadIdx.x;
    if (e < Ee) {
        int s = src[e], d = dst[e];
        int pos = atomicAdd(&g_cursor[d], 1);
        float w = -g_dinv[s] * g_dinv[d];
        g_epack[pos] = make_int2(s, __float_as_int(w));
    }
}

__global__ void k_pad() {                // fill zero-weight padding entries
    int i = blockIdx.x * blockDim.x + threadIdx.x;
    if (i < Nn) {
        int start = g_rowptr[i] + g_indeg[i];
        int end   = g_rowptr[i + 1];
        for (int e = start; e < end; e++)
            g_epack[e] = make_int2(0, 0);
    }
}

// ---------------- layer 1 (F = 1) ----------------
__global__ void k_prop_scalar(const float* __restrict__ tin, const float* __restrict__ tprev,
                              float* __restrict__ tout, float alpha, float beta) {
    int warp = threadIdx.x >> 5, lane = threadIdx.x & 31;
    int n = blockIdx.x * (blockDim.x >> 5) + warp;
    int s0 = g_rowptr[n], s1 = g_rowptr[n + 1];
    float acc = 0.0f;
    for (int e = s0 + lane; e < s1; e += 32) {
        int2 p = __ldg(&g_epack[e]);
        acc = fmaf(__int_as_float(p.y), __ldg(&tin[p.x]), acc);
    }
#pragma unroll
    for (int off = 16; off > 0; off >>= 1)
        acc += __shfl_xor_sync(0xffffffffu, acc, off);
    if (lane == 0)
        tout[n] = alpha * acc - beta * tprev[n];
}

__global__ void k_layer1_out(const float* __restrict__ x, const float* __restrict__ W1,
                             const float* __restrict__ b1, float* __restrict__ h,
                             __half* __restrict__ h16) {
    int warp = threadIdx.x >> 5, lane = threadIdx.x & 31;
    int n = blockIdx.x * (blockDim.x >> 5) + warp;
    float acc = b1[lane] + x[n] * W1[lane];
#pragma unroll
    for (int k = 1; k < 5; k++)
        acc = fmaf(g_ts[k][n], W1[k * HID + lane], acc);
    float v = fmaxf(acc, 0.0f);
    h[n * HID + lane] = v;
    h16[n * HID + lane] = __float2half(v);
}

// ---------------- layers 2/3 (F = 32) ----------------
// Scalar-lane prop: warp = 1 node, lane = feature. Edge packs loaded
// lane-cooperatively (LDG.64/32 edges/lane) and shuffle-broadcast; feature row
// gathered as one coalesced 64B LDG.U16 per edge; fp32 accumulate.
__device__ __forceinline__ float prop_h(const __half* __restrict__ tin, int n, int lane) {
    int s0 = __ldg(&g_rowptr[n]), s1 = __ldg(&g_rowptr[n + 1]);
    float acc = 0.0f;
    for (int base = s0; base < s1; base += 32) {
        int e = base + lane;
        int2 p = make_int2(0, 0);
        if (e < s1) p = __ldg(&g_epack[e]);
        int cnt = min(32, s1 - base);      // multiple of 4 (rows padded)
        for (int t = 0; t < cnt; t += 4) {
#pragma unroll
            for (int u = 0; u < 4; u++) {
                int   ss = __shfl_sync(0xffffffffu, p.x, t + u);
                float ww = __int_as_float(__shfl_sync(0xffffffffu, p.y, t + u));
                float v  = __half2float(__ldg(&tin[ss * HID + lane]));
                acc = fmaf(ww, v, acc);
            }
        }
    }
    return acc;
}

// o += val @ W; lane owns output column = lane; W column preloaded in regs.
__device__ __forceinline__ float mm32r(float val, const float* __restrict__ wreg) {
    float o = 0.f;
#pragma unroll
    for (int i = 0; i < HID; i++)
        o = fmaf(__shfl_sync(0xffffffffu, val, i), wreg[i], o);
    return o;
}

// First step: T1 = prop(T0). outacc = T0@W0 + T1@W1; tout = T1 (fp32+fp16).
__global__ void __launch_bounds__(256) k_cheb_first(
        const float* __restrict__ tin32, const __half* __restrict__ tin16,
        float* __restrict__ tout32, __half* __restrict__ tout16,
        const float* __restrict__ W01, float* __restrict__ outacc) {
    int warp = threadIdx.x >> 5, lane = threadIdx.x & 31;
    int n = blockIdx.x * (blockDim.x >> 5) + warp;
    float w0[HID], w1[HID];
#pragma unroll
    for (int i = 0; i < HID; i++) {
        w0[i] = __ldg(&W01[i * HID + lane]);
        w1[i] = __ldg(&W01[HID * HID + i * HID + lane]);
    }
    float t1 = prop_h(tin16, n, lane);
    float t0 = tin32[n * HID + lane];
    tout32[n * HID + lane] = t1;
    tout16[n * HID + lane] = __float2half(t1);
    outacc[n * HID + lane] = mm32r(t0, w0) + mm32r(t1, w1);
}

// Middle step: Tk = 2*prop(T_{k-1}) - T_{k-2}. outacc += Tk@Wk; tout = Tk.
__global__ void __launch_bounds__(256) k_cheb_mid(
        const __half* __restrict__ tin16, const float* __restrict__ tprev,
        float* __restrict__ tout32, __half* __restrict__ tout16,
        const float* __restrict__ W, float* __restrict__ outacc) {
    int warp = threadIdx.x >> 5, lane = threadIdx.x & 31;
    int n = blockIdx.x * (blockDim.x >> 5) + warp;
    float wreg[HID];
#pragma unroll
    for (int i = 0; i < HID; i++) wreg[i] = __ldg(&W[i * HID + lane]);
    float p = prop_h(tin16, n, lane);
    float val = 2.0f * p - tprev[n * HID + lane];
    tout32[n * HID + lane] = val;
    tout16[n * HID + lane] = __float2half(val);
    outacc[n * HID + lane] += mm32r(val, wreg);
}

// Last step: Tk = 2*prop(T_{k-1}) - T_{k-2}. H = act(outacc + Tk@Wk + bias).
__global__ void __launch_bounds__(256) k_cheb_last(
        const __half* __restrict__ tin16, const float* __restrict__ tprev,
        const float* __restrict__ W, const float* __restrict__ outacc,
        const float* __restrict__ bias, int relu,
        float* __restrict__ hout, __half* __restrict__ hout16) {
    int warp = threadIdx.x >> 5, lane = threadIdx.x & 31;
    int n = blockIdx.x * (blockDim.x >> 5) + warp;
    float wreg[HID];
#pragma unroll
    for (int i = 0; i < HID; i++) wreg[i] = __ldg(&W[i * HID + lane]);
    float p = prop_h(tin16, n, lane);
    float val = 2.0f * p - tprev[n * HID + lane];
    float o = outacc[n * HID + lane] + mm32r(val, wreg) + bias[lane];
    if (relu) o = fmaxf(o, 0.0f);
    hout[n * HID + lane] = o;
    hout16[n * HID + lane] = __float2half(o);
}

// ---------------- final linear (8 x 262144) @ (262144 x 33) ----------------
__global__ void k_out_init(float* __restrict__ out, const float* __restrict__ bl) {
    int t = threadIdx.x;
    if (t < GNUM * OSZ) out[t] = bl[t % OSZ];
}

__global__ void k_final(const float* __restrict__ h, const float* __restrict__ Wl,
                        float* __restrict__ out) {
    int t = threadIdx.x;
    if (t >= GNUM * OSZ) return;
    int g = t / OSZ, j = t % OSZ;
    const int CH = (ISZ * HID) / gridDim.x;
    int i0 = blockIdx.x * CH;
    const float* hg = h + g * (ISZ * HID);
    float acc = 0.0f;
#pragma unroll 4
    for (int i = i0; i < i0 + CH; i++)
        acc = fmaf(__ldg(&hg[i]), __ldg(&Wl[i * OSZ + j]), acc);
    atomicAdd(&out[t], acc);
}

// ---------------- launch ----------------
extern "C" void kernel_launch(void* const* d_in, const int* in_sizes, int n_in,
                              void* d_out, int out_size) {
    const float* x  = (const float*)d_in[0];
    const int*   ei = (const int*)  d_in[1];
    const float* W1 = (const float*)d_in[3];
    const float* b1 = (const float*)d_in[4];
    const float* W2 = (const float*)d_in[5];
    const float* b2 = (const float*)d_in[6];
    const float* W3 = (const float*)d_in[7];
    const float* b3 = (const float*)d_in[8];
    const float* Wl = (const float*)d_in[9];
    const float* bl = (const float*)d_in[10];
    float* out = (float*)d_out;

    const int* src = ei;
    const int* dst = ei + Ee;

    float *buf0, *buf1, *buf2, *acc, *ts;
    __half *ha, *hb;
    void *degp, *indegp;
    cudaGetSymbolAddress((void**)&buf0, g_buf0);
    cudaGetSymbolAddress((void**)&buf1, g_buf1);
    cudaGetSymbolAddress((void**)&buf2, g_buf2);
    cudaGetSymbolAddress((void**)&acc,  g_accb);
    cudaGetSymbolAddress((void**)&ts,   g_ts);
    cudaGetSymbolAddress((void**)&ha,   g_h16a);
    cudaGetSymbolAddress((void**)&hb,   g_h16b);
    cudaGetSymbolAddress(&degp,   g_deg);
    cudaGetSymbolAddress(&indegp, g_indeg);

    const int EB = Ee / 256;      // edge-parallel blocks
    const int NB = Nn / 256;      // node-parallel blocks
    const int PB = Nn / 8;        // warp-per-node blocks

    // --- graph preprocessing: degrees, dinv, padded CSR by dst ---
    cudaMemsetAsync(degp,   0, Nn * sizeof(int));
    cudaMemsetAsync(indegp, 0, Nn * sizeof(int));
    k_hist   <<<EB, 256>>>(src, dst);
    k_dinv   <<<NB, 256>>>();
    k_bsum   <<<256, 256>>>();
    k_bscan  <<<1, 256>>>();
    k_rowptr <<<256, 256>>>();
    k_scatter<<<EB, 256>>>(src, dst);
    k_pad    <<<NB, 256>>>();

    // --- layer 1 (scalar features) ---
    k_prop_scalar<<<PB, 256>>>(x,            x,            ts + 1 * Nn, 1.f, 0.f);
    k_prop_scalar<<<PB, 256>>>(ts + 1 * Nn,  x,            ts + 2 * Nn, 2.f, 1.f);
    k_prop_scalar<<<PB, 256>>>(ts + 2 * Nn,  ts + 1 * Nn,  ts + 3 * Nn, 2.f, 1.f);
    k_prop_scalar<<<PB, 256>>>(ts + 3 * Nn,  ts + 2 * Nn,  ts + 4 * Nn, 2.f, 1.f);
    k_layer1_out <<<PB, 256>>>(x, W1, b1, buf0, ha);       // H1 -> buf0 / ha

    // --- layer 2 (T0 = buf0 = H1, fp16 in ha) ---
    k_cheb_first<<<PB, 256>>>(buf0, ha, buf1, hb, W2, acc);              // T1 -> buf1/hb
    k_cheb_mid  <<<PB, 256>>>(hb, buf0, buf0, ha, W2 + 2048, acc);       // T2 -> buf0/ha
    k_cheb_mid  <<<PB, 256>>>(ha, buf1, buf1, hb, W2 + 3072, acc);       // T3 -> buf1/hb
    k_cheb_last <<<PB, 256>>>(hb, buf0, W2 + 4096, acc, b2, 1, buf2, ha);// H2 -> buf2/ha

    // --- layer 3 (T0 = buf2 = H2, fp16 in ha) ---
    k_cheb_first<<<PB, 256>>>(buf2, ha, buf0, hb, W3, acc);              // T1 -> buf0/hb
    k_cheb_mid  <<<PB, 256>>>(hb, buf2, buf2, ha, W3 + 2048, acc);       // T2 -> buf2/ha
    k_cheb_mid  <<<PB, 256>>>(ha, buf0, buf0, hb, W3 + 3072, acc);       // T3 -> buf0/hb
    k_cheb_last <<<PB, 256>>>(hb, buf2, W3 + 4096, acc, b3, 0, buf1, ha);// H3 -> buf1

    // --- final linear ---
    k_out_init<<<1, 264>>>(out, bl);
    k_final   <<<512, 264>>>(buf1, Wl, out);
}

// round 7
// speedup vs baseline: 2.1806x; 2.1806x over previous
#include <cuda_runtime.h>
#include <cuda_fp16.h>

// ---------------- problem constants (fixed shapes) ----------------
#define Nn   65536          // total nodes
#define Ee   2097152        // edges
#define HID  32
#define GNUM 8
#define ISZ  8192
#define OSZ  33
#define FEAT (Nn * HID)

// ---------------- static device scratch ----------------
__device__ __align__(128) float g_dinv[Nn];
__device__ __align__(128) int   g_deg[Nn];
__device__ __align__(128) int   g_indeg[Nn];
__device__ int   g_bsum[256];
__device__ int   g_boff[256];
__device__ __align__(128) int   g_rowptr[Nn + 1];
__device__ int   g_cursor[Nn];
__device__ __align__(128) unsigned int g_epk[Ee];     // src(16b) | half-weight(16b)
__device__ __align__(128) float g_ts[5][Nn];          // scalar Chebyshev terms, layer 1
__device__ __align__(128) float g_buf0[FEAT];
__device__ __align__(128) float g_buf1[FEAT];
__device__ __align__(128) float g_buf2[FEAT];
__device__ __align__(128) float g_accb[FEAT];
__device__ __align__(128) __half g_h16a[FEAT];        // fp16 gather copies (ping-pong)
__device__ __align__(128) __half g_h16b[FEAT];

// ---------------- setup kernels ----------------
__global__ void k_hist(const int* __restrict__ src, const int* __restrict__ dst) {
    int e = blockIdx.x * blockDim.x + threadIdx.x;
    if (e < Ee) {
        atomicAdd(&g_deg[src[e]], 1);
        atomicAdd(&g_indeg[dst[e]], 1);
    }
}

__global__ void k_dinv() {
    int i = blockIdx.x * blockDim.x + threadIdx.x;
    if (i < Nn) {
        int d = g_deg[i];
        g_dinv[i] = (d > 0) ? rsqrtf((float)d) : 0.0f;
    }
}

// ---- 3-stage parallel exclusive scan of g_indeg -> g_rowptr / g_cursor ----
__global__ void k_bsum() {               // 256 blocks x 256 threads
    __shared__ int sh[256];
    int t = threadIdx.x;
    sh[t] = g_indeg[blockIdx.x * 256 + t];
    __syncthreads();
    for (int off = 128; off > 0; off >>= 1) {
        if (t < off) sh[t] += sh[t + off];
        __syncthreads();
    }
    if (t == 0) g_bsum[blockIdx.x] = sh[0];
}

__global__ void k_bscan() {              // 1 block x 256 threads
    __shared__ int sh[256];
    int t = threadIdx.x;
    sh[t] = g_bsum[t];
    __syncthreads();
    for (int off = 1; off < 256; off <<= 1) {
        int v = (t >= off) ? sh[t - off] : 0;
        __syncthreads();
        sh[t] += v;
        __syncthreads();
    }
    g_boff[t] = (t == 0) ? 0 : sh[t - 1];
}

__global__ void k_rowptr() {             // 256 blocks x 256 threads
    __shared__ int sh[256];
    int t = threadIdx.x;
    int i = blockIdx.x * 256 + t;
    int v = g_indeg[i];
    sh[t] = v;
    __syncthreads();
    for (int off = 1; off < 256; off <<= 1) {
        int u = (t >= off) ? sh[t - off] : 0;
        __syncthreads();
        sh[t] += u;
        __syncthreads();
    }
    int excl = sh[t] - v + g_boff[blockIdx.x];
    g_rowptr[i] = excl;
    g_cursor[i] = excl;
    if (i == 0) g_rowptr[Nn] = Ee;
}

__global__ void k_scatter(const int* __restrict__ src, const int* __restrict__ dst) {
    int e = blockIdx.x * blockDim.x + threadIdx.x;
    if (e < Ee) {
        int s = src[e], d = dst[e];
        int pos = atomicAdd(&g_cursor[d], 1);
        float w = -g_dinv[s] * g_dinv[d];
        unsigned short wh = __half_as_ushort(__float2half(w));
        g_epk[pos] = (unsigned int)s | ((unsigned int)wh << 16);
    }
}

__device__ __forceinline__ void unpack_edge(unsigned int u, int& s, float& w) {
    s = (int)(u & 0xFFFFu);
    w = __half2float(__ushort_as_half((unsigned short)(u >> 16)));
}

// ---------------- layer 1 (F = 1) ----------------
__global__ void k_prop_scalar(const float* __restrict__ tin, const float* __restrict__ tprev,
                              float* __restrict__ tout, float alpha, float beta) {
    int warp = threadIdx.x >> 5, lane = threadIdx.x & 31;
    int n = blockIdx.x * (blockDim.x >> 5) + warp;
    int s0 = g_rowptr[n], s1 = g_rowptr[n + 1];
    float acc = 0.0f;
    for (int e = s0 + lane; e < s1; e += 32) {
        int s; float w;
        unpack_edge(__ldg(&g_epk[e]), s, w);
        acc = fmaf(w, __ldg(&tin[s]), acc);
    }
#pragma unroll
    for (int off = 16; off > 0; off >>= 1)
        acc += __shfl_xor_sync(0xffffffffu, acc, off);
    if (lane == 0)
        tout[n] = alpha * acc - beta * tprev[n];
}

__global__ void k_layer1_out(const float* __restrict__ x, const float* __restrict__ W1,
                             const float* __restrict__ b1, float* __restrict__ h,
                             __half* __restrict__ h16) {
    int warp = threadIdx.x >> 5, lane = threadIdx.x & 31;
    int n = blockIdx.x * (blockDim.x >> 5) + warp;
    float acc = b1[lane] + x[n] * W1[lane];
#pragma unroll
    for (int k = 1; k < 5; k++)
        acc = fmaf(g_ts[k][n], W1[k * HID + lane], acc);
    float v = fmaxf(acc, 0.0f);
    h[n * HID + lane] = v;
    h16[n * HID + lane] = __float2half(v);
}

// ---------------- layers 2/3 (F = 32) ----------------
// warp = 4 nodes, 8-lane group per node; lane = (g, q), q = feature-quarter.
// fp16 gather rows: group reads one 64B line per edge (uint2 = 4 halfs/lane),
// converts, accumulates fp32. Edge stream is a 4B broadcast LDG per edge.
__device__ __forceinline__ float4 cheb_prop4h(const __half* __restrict__ tin, int n, int q) {
    int s0 = __ldg(&g_rowptr[n]), s1 = __ldg(&g_rowptr[n + 1]);
    const uint2* tin2 = (const uint2*)tin;
    float4 a = make_float4(0.f, 0.f, 0.f, 0.f);
#pragma unroll 4
    for (int e = s0; e < s1; e++) {
        int s; float w;
        unpack_edge(__ldg(&g_epk[e]), s, w);
        uint2 rv = __ldg(&tin2[s * 8 + q]);
        __half2 h01 = *reinterpret_cast<__half2*>(&rv.x);
        __half2 h23 = *reinterpret_cast<__half2*>(&rv.y);
        float2 f01 = __half22float2(h01);
        float2 f23 = __half22float2(h23);
        a.x = fmaf(w, f01.x, a.x);
        a.y = fmaf(w, f01.y, a.y);
        a.z = fmaf(w, f23.x, a.z);
        a.w = fmaf(w, f23.y, a.w);
    }
    return a;
}

// o += val @ W within an 8-lane group: lane q holds features 4q..4q+3 of val/o.
__device__ __forceinline__ void mm32g(float4& o, float4 val, const float* __restrict__ Wsh,
                                      int lane, int q) {
    int gbase = lane & 24;
#pragma unroll
    for (int i = 0; i < HID; i++) {
        float comp = (i & 3) == 0 ? val.x : (i & 3) == 1 ? val.y : (i & 3) == 2 ? val.z : val.w;
        float vi = __shfl_sync(0xffffffffu, comp, gbase + (i >> 2));
        float4 wv = ((const float4*)Wsh)[i * 8 + q];
        o.x = fmaf(vi, wv.x, o.x);
        o.y = fmaf(vi, wv.y, o.y);
        o.z = fmaf(vi, wv.z, o.z);
        o.w = fmaf(vi, wv.w, o.w);
    }
}

__device__ __forceinline__ void store16(__half* __restrict__ dst, int idx, float4 v) {
    __half2 lo = __floats2half2_rn(v.x, v.y);
    __half2 hi = __floats2half2_rn(v.z, v.w);
    uint2 pk;
    pk.x = *reinterpret_cast<unsigned int*>(&lo);
    pk.y = *reinterpret_cast<unsigned int*>(&hi);
    ((uint2*)dst)[idx] = pk;
}

// First step: T1 = prop(T0). outacc = T0@W0 + T1@W1; tout = T1 (fp32 + fp16).
__global__ void __launch_bounds__(256) k_cheb_first(
        const float* __restrict__ tin32, const __half* __restrict__ tin16,
        float* __restrict__ tout32, __half* __restrict__ tout16,
        const float* __restrict__ W01, float* __restrict__ outacc) {
    __shared__ float Wsh[2 * HID * HID];
    for (int i = threadIdx.x; i < 2 * HID * HID; i += blockDim.x) Wsh[i] = W01[i];
    __syncthreads();
    int warp = threadIdx.x >> 5, lane = threadIdx.x & 31;
    int g = lane >> 3, q = lane & 7;
    int n = (blockIdx.x * (blockDim.x >> 5) + warp) * 4 + g;
    float4 t1 = cheb_prop4h(tin16, n, q);
    float4 t0 = ((const float4*)tin32)[n * 8 + q];
    ((float4*)tout32)[n * 8 + q] = t1;
    store16(tout16, n * 8 + q, t1);
    float4 o = make_float4(0.f, 0.f, 0.f, 0.f);
    mm32g(o, t0, Wsh, lane, q);
    mm32g(o, t1, Wsh + HID * HID, lane, q);
    ((float4*)outacc)[n * 8 + q] = o;
}

// Middle step: Tk = 2*prop(T_{k-1}) - T_{k-2}. outacc += Tk@Wk; tout = Tk.
__global__ void __launch_bounds__(256) k_cheb_mid(
        const __half* __restrict__ tin16, const float* __restrict__ tprev,
        float* __restrict__ tout32, __half* __restrict__ tout16,
        const float* __restrict__ W, float* __restrict__ outacc) {
    __shared__ float Wsh[HID * HID];
    for (int i = threadIdx.x; i < HID * HID; i += blockDim.x) Wsh[i] = W[i];
    __syncthreads();
    int warp = threadIdx.x >> 5, lane = threadIdx.x & 31;
    int g = lane >> 3, q = lane & 7;
    int n = (blockIdx.x * (blockDim.x >> 5) + warp) * 4 + g;
    float4 p = cheb_prop4h(tin16, n, q);
    float4 tp = ((const float4*)tprev)[n * 8 + q];
    float4 val = make_float4(2.f * p.x - tp.x, 2.f * p.y - tp.y,
                             2.f * p.z - tp.z, 2.f * p.w - tp.w);
    ((float4*)tout32)[n * 8 + q] = val;
    store16(tout16, n * 8 + q, val);
    float4 o = ((const float4*)outacc)[n * 8 + q];
    mm32g(o, val, Wsh, lane, q);
    ((float4*)outacc)[n * 8 + q] = o;
}

// Last step: Tk = 2*prop(T_{k-1}) - T_{k-2}. H = act(outacc + Tk@Wk + bias).
__global__ void __launch_bounds__(256) k_cheb_last(
        const __half* __restrict__ tin16, const float* __restrict__ tprev,
        const float* __restrict__ W, const float* __restrict__ outacc,
        const float* __restrict__ bias, int relu,
        float* __restrict__ hout, __half* __restrict__ hout16) {
    __shared__ float Wsh[HID * HID];
    for (int i = threadIdx.x; i < HID * HID; i += blockDim.x) Wsh[i] = W[i];
    __syncthreads();
    int warp = threadIdx.x >> 5, lane = threadIdx.x & 31;
    int g = lane >> 3, q = lane & 7;
    int n = (blockIdx.x * (blockDim.x >> 5) + warp) * 4 + g;
    float4 p = cheb_prop4h(tin16, n, q);
    float4 tp = ((const float4*)tprev)[n * 8 + q];
    float4 val = make_float4(2.f * p.x - tp.x, 2.f * p.y - tp.y,
                             2.f * p.z - tp.z, 2.f * p.w - tp.w);
    float4 o = ((const float4*)outacc)[n * 8 + q];
    mm32g(o, val, Wsh, lane, q);
    float4 bv = ((const float4*)bias)[q];
    o.x += bv.x; o.y += bv.y; o.z += bv.z; o.w += bv.w;
    if (relu) {
        o.x = fmaxf(o.x, 0.f); o.y = fmaxf(o.y, 0.f);
        o.z = fmaxf(o.z, 0.f); o.w = fmaxf(o.w, 0.f);
    }
    ((float4*)hout)[n * 8 + q] = o;
    store16(hout16, n * 8 + q, o);
}

// ---------------- final linear (8 x 262144) @ (262144 x 33) ----------------
__global__ void k_out_init(float* __restrict__ out, const float* __restrict__ bl) {
    int t = threadIdx.x;
    if (t < GNUM * OSZ) out[t] = bl[t % OSZ];
}

__global__ void k_final(const float* __restrict__ h, const float* __restrict__ Wl,
                        float* __restrict__ out) {
    int t = threadIdx.x;
    if (t >= GNUM * OSZ) return;
    int g = t / OSZ, j = t % OSZ;
    const int CH = (ISZ * HID) / gridDim.x;
    int i0 = blockIdx.x * CH;
    const float* hg = h + g * (ISZ * HID);
    float acc = 0.0f;
#pragma unroll 4
    for (int i = i0; i < i0 + CH; i++)
        acc = fmaf(__ldg(&hg[i]), __ldg(&Wl[i * OSZ + j]), acc);
    atomicAdd(&out[t], acc);
}

// ---------------- launch ----------------
extern "C" void kernel_launch(void* const* d_in, const int* in_sizes, int n_in,
                              void* d_out, int out_size) {
    const float* x  = (const float*)d_in[0];
    const int*   ei = (const int*)  d_in[1];
    const float* W1 = (const float*)d_in[3];
    const float* b1 = (const float*)d_in[4];
    const float* W2 = (const float*)d_in[5];
    const float* b2 = (const float*)d_in[6];
    const float* W3 = (const float*)d_in[7];
    const float* b3 = (const float*)d_in[8];
    const float* Wl = (const float*)d_in[9];
    const float* bl = (const float*)d_in[10];
    float* out = (float*)d_out;

    const int* src = ei;
    const int* dst = ei + Ee;

    float *buf0, *buf1, *buf2, *acc, *ts;
    __half *ha, *hb;
    void *degp, *indegp;
    cudaGetSymbolAddress((void**)&buf0, g_buf0);
    cudaGetSymbolAddress((void**)&buf1, g_buf1);
    cudaGetSymbolAddress((void**)&buf2, g_buf2);
    cudaGetSymbolAddress((void**)&acc,  g_accb);
    cudaGetSymbolAddress((void**)&ts,   g_ts);
    cudaGetSymbolAddress((void**)&ha,   g_h16a);
    cudaGetSymbolAddress((void**)&hb,   g_h16b);
    cudaGetSymbolAddress(&degp,   g_deg);
    cudaGetSymbolAddress(&indegp, g_indeg);

    const int EB = Ee / 256;      // edge-parallel blocks
    const int NB = Nn / 256;      // node-parallel blocks
    const int PB = Nn / 8;        // warp-per-node blocks (layer-1 kernels)
    const int QB = Nn / 32;       // 4-nodes-per-warp blocks (heavy props)

    // --- graph preprocessing: degrees, dinv, CSR by dst ---
    cudaMemsetAsync(degp,   0, Nn * sizeof(int));
    cudaMemsetAsync(indegp, 0, Nn * sizeof(int));
    k_hist   <<<EB, 256>>>(src, dst);
    k_dinv   <<<NB, 256>>>();
    k_bsum   <<<256, 256>>>();
    k_bscan  <<<1, 256>>>();
    k_rowptr <<<256, 256>>>();
    k_scatter<<<EB, 256>>>(src, dst);

    // --- layer 1 (scalar features) ---
    k_prop_scalar<<<PB, 256>>>(x,            x,            ts + 1 * Nn, 1.f, 0.f);
    k_prop_scalar<<<PB, 256>>>(ts + 1 * Nn,  x,            ts + 2 * Nn, 2.f, 1.f);
    k_prop_scalar<<<PB, 256>>>(ts + 2 * Nn,  ts + 1 * Nn,  ts + 3 * Nn, 2.f, 1.f);
    k_prop_scalar<<<PB, 256>>>(ts + 3 * Nn,  ts + 2 * Nn,  ts + 4 * Nn, 2.f, 1.f);
    k_layer1_out <<<PB, 256>>>(x, W1, b1, buf0, ha);       // H1 -> buf0 / ha

    // --- layer 2 (T0 = buf0 = H1, fp16 in ha) ---
    k_cheb_first<<<QB, 256>>>(buf0, ha, buf1, hb, W2, acc);              // T1 -> buf1/hb
    k_cheb_mid  <<<QB, 256>>>(hb, buf0, buf0, ha, W2 + 2048, acc);       // T2 -> buf0/ha
    k_cheb_mid  <<<QB, 256>>>(ha, buf1, buf1, hb, W2 + 3072, acc);       // T3 -> buf1/hb
    k_cheb_last <<<QB, 256>>>(hb, buf0, W2 + 4096, acc, b2, 1, buf2, ha);// H2 -> buf2/ha

    // --- layer 3 (T0 = buf2 = H2, fp16 in ha) ---
    k_cheb_first<<<QB, 256>>>(buf2, ha, buf0, hb, W3, acc);              // T1 -> buf0/hb
    k_cheb_mid  <<<QB, 256>>>(hb, buf2, buf2, ha, W3 + 2048, acc);       // T2 -> buf2/ha
    k_cheb_mid  <<<QB, 256>>>(ha, buf0, buf0, hb, W3 + 3072, acc);       // T3 -> buf0/hb
    k_cheb_last <<<QB, 256>>>(hb, buf2, W3 + 4096, acc, b3, 0, buf1, ha);// H3 -> buf1

    // --- final linear ---
    k_out_init<<<1, 264>>>(out, bl);
    k_final   <<<512, 264>>>(buf1, Wl, out);
}